// round 5
// baseline (speedup 1.0000x reference)
#include <cuda_runtime.h>
#include <math.h>

// Problem constants
#define NUM_EMBED   512
#define EMBED_DIM   64
#define BATCH       4
#define SPATIAL     32768           // 32*32*32
#define N_TOKENS    (BATCH*SPATIAL) // 131072
#define Q_ELEMS     (BATCH*EMBED_DIM*SPATIAL) // 8388608

// Output offsets (tuple flattened, float32)
#define OFF_LOSS      0
#define OFF_Q         1
#define OFF_PERP      (OFF_Q + Q_ELEMS)                 // 8388609
#define OFF_IDX       (OFF_PERP + 1)                    // 8388610
#define OFF_NEWEMBED  (OFF_IDX + N_TOKENS)              // 8519682
#define OFF_CS        (OFF_NEWEMBED + NUM_EMBED*EMBED_DIM) // 8552450
#define OFF_EA        (OFF_CS + NUM_EMBED)              // 8552962

#define DECAY           0.99f
#define ONE_MINUS_DECAY 0.01f
#define COMMIT_COST     0.25f
#define LAPLACE_ALPHA   1e-5f

// Scratch (device globals — no allocations allowed)
__device__ float  g_counts[NUM_EMBED];
__device__ float  g_dw[NUM_EMBED * EMBED_DIM];
__device__ double g_loss;

// ---------------------------------------------------------------------------
// Packed f32x2 helpers (sm_103a FFMA2 path — ptxas never emits this from C++)
// ---------------------------------------------------------------------------
typedef unsigned long long u64;

static __device__ __forceinline__ u64 fma2(u64 a, u64 b, u64 c) {
    u64 d;
    asm("fma.rn.f32x2 %0, %1, %2, %3;" : "=l"(d) : "l"(a), "l"(b), "l"(c));
    return d;
}
static __device__ __forceinline__ u64 pack2(float lo, float hi) {
    u64 r;
    asm("mov.b64 %0, {%1, %2};" : "=l"(r) : "f"(lo), "f"(hi));
    return r;
}
static __device__ __forceinline__ float2 unpack2(u64 v) {
    float2 r;
    asm("mov.b64 {%0, %1}, %2;" : "=f"(r.x), "=f"(r.y) : "l"(v));
    return r;
}

// ---------------------------------------------------------------------------
// Kernel 0: zero scratch (graph replays require re-zeroing every launch)
// ---------------------------------------------------------------------------
__global__ void vq_zero_kernel() {
    int i = blockIdx.x * blockDim.x + threadIdx.x;
    if (i < NUM_EMBED * EMBED_DIM) g_dw[i] = 0.0f;
    if (i < NUM_EMBED)             g_counts[i] = 0.0f;
    if (i == 0)                    g_loss = 0.0;
}

// ---------------------------------------------------------------------------
// Kernel 1: fused distance/argmin via packed f32x2 FMA
// Grid: 256 CTAs x 512 threads, 1 token per thread (4 warps/SMSP).
// smem: negated embed [512][64] + half-norms [512] = 133120 B (occ = 1)
// ---------------------------------------------------------------------------
#define MAIN_THREADS 512
#define MAIN_CTAS    (N_TOKENS / MAIN_THREADS)   // 256
#define SMEM_BYTES   ((NUM_EMBED * EMBED_DIM + NUM_EMBED) * 4)

extern __shared__ float smem_dyn[];

__global__ void __launch_bounds__(MAIN_THREADS, 1)
vq_main_kernel(const float* __restrict__ inputs,
               const float* __restrict__ embed,
               float* __restrict__ out)
{
    float* ne    = smem_dyn;                          // -embed, [k*64 + c]
    float* halfn = smem_dyn + NUM_EMBED * EMBED_DIM;  // 0.5*||e_k||^2

    // Load negated embed into shared (coalesced float4)
    {
        const float4* src = reinterpret_cast<const float4*>(embed);
        float4* dst = reinterpret_cast<float4*>(ne);
        for (int i = threadIdx.x; i < NUM_EMBED * EMBED_DIM / 4; i += blockDim.x) {
            float4 v = src[i];
            v.x = -v.x; v.y = -v.y; v.z = -v.z; v.w = -v.w;
            dst[i] = v;
        }
    }
    __syncthreads();
    // Half norms (sequential c order)
    for (int k = threadIdx.x; k < NUM_EMBED; k += blockDim.x) {
        const float* row = ne + k * EMBED_DIM;
        float s = 0.0f;
        #pragma unroll
        for (int c = 0; c < EMBED_DIM; c++) s = fmaf(row[c], row[c], s);
        halfn[k] = 0.5f * s;
    }
    __syncthreads();

    // Token for this thread
    const int n = blockIdx.x * MAIN_THREADS + threadIdx.x;
    const int b = n >> 15;
    const int s = n & (SPATIAL - 1);
    const float* xin = inputs + (size_t)b * (EMBED_DIM * SPATIAL) + s;

    // Load token vector, packed as f32x2 dim-pairs (32 x u64 = 64 regs)
    u64 xp[EMBED_DIM / 2];
    #pragma unroll
    for (int c2 = 0; c2 < EMBED_DIM / 2; c2++) {
        const float lo = xin[(size_t)(2 * c2 + 0) * SPATIAL];
        const float hi = xin[(size_t)(2 * c2 + 1) * SPATIAL];
        xp[c2] = pack2(lo, hi);
    }

    // Argmin: dist_k = 0.5||e_k||^2 - x.e_k   (ne holds -e)
    float best = 3.402823466e38f;
    int bestk = 0;

    #pragma unroll 1
    for (int k = 0; k < NUM_EMBED; k += 4) {
        const ulonglong2* __restrict__ r0 = reinterpret_cast<const ulonglong2*>(ne + (size_t)(k + 0) * EMBED_DIM);
        const ulonglong2* __restrict__ r1 = reinterpret_cast<const ulonglong2*>(ne + (size_t)(k + 1) * EMBED_DIM);
        const ulonglong2* __restrict__ r2 = reinterpret_cast<const ulonglong2*>(ne + (size_t)(k + 2) * EMBED_DIM);
        const ulonglong2* __restrict__ r3 = reinterpret_cast<const ulonglong2*>(ne + (size_t)(k + 3) * EMBED_DIM);
        u64 a0 = 0ull, a1 = 0ull, a2 = 0ull, a3 = 0ull;
        #pragma unroll
        for (int c4 = 0; c4 < EMBED_DIM / 4; c4++) {
            const ulonglong2 v0 = r0[c4];   // one LDS.128 = two f32x2 operands
            const ulonglong2 v1 = r1[c4];
            const ulonglong2 v2 = r2[c4];
            const ulonglong2 v3 = r3[c4];
            const u64 xA = xp[2 * c4 + 0];
            const u64 xB = xp[2 * c4 + 1];
            a0 = fma2(xA, v0.x, a0);
            a1 = fma2(xA, v1.x, a1);
            a2 = fma2(xA, v2.x, a2);
            a3 = fma2(xA, v3.x, a3);
            a0 = fma2(xB, v0.y, a0);
            a1 = fma2(xB, v1.y, a1);
            a2 = fma2(xB, v2.y, a2);
            a3 = fma2(xB, v3.y, a3);
        }
        const float2 f0 = unpack2(a0);
        const float2 f1 = unpack2(a1);
        const float2 f2 = unpack2(a2);
        const float2 f3 = unpack2(a3);
        const float d0 = halfn[k + 0] + f0.x + f0.y;
        const float d1 = halfn[k + 1] + f1.x + f1.y;
        const float d2 = halfn[k + 2] + f2.x + f2.y;
        const float d3 = halfn[k + 3] + f3.x + f3.y;
        // strict < keeps first (lowest-k) minimum, matching jnp.argmin
        if (d0 < best) { best = d0; bestk = k + 0; }
        if (d1 < best) { best = d1; bestk = k + 1; }
        if (d2 < best) { best = d2; bestk = k + 2; }
        if (d3 < best) { best = d3; bestk = k + 3; }
    }

    // ---- Epilogue ----
    out[OFF_IDX + n] = (float)bestk;
    atomicAdd(&g_counts[bestk], 1.0f);

    const float2* erow = reinterpret_cast<const float2*>(ne + (size_t)bestk * EMBED_DIM);
    float* qout = out + OFF_Q + (size_t)b * (EMBED_DIM * SPATIAL) + s;
    float* dwrow = g_dw + (size_t)bestk * EMBED_DIM;

    float lsum = 0.0f;
    #pragma unroll
    for (int c2 = 0; c2 < EMBED_DIM / 2; c2++) {
        const float2 nev = erow[c2];        // -e
        const float2 xv  = unpack2(xp[c2]);
        // d = e - x  (reference computes quantized_cf - inputs in fp32)
        const float d0 = (-nev.x) - xv.x;
        const float d1 = (-nev.y) - xv.y;
        lsum = fmaf(d0, d0, lsum);
        lsum = fmaf(d1, d1, lsum);
        const int c = c2 * 2;
        // straight-through: out = x + (q - x), matching reference rounding
        qout[(size_t)(c + 0) * SPATIAL] = xv.x + d0;
        qout[(size_t)(c + 1) * SPATIAL] = xv.y + d1;
        // dw segment-sum of flat_input
        atomicAdd(&dwrow[c + 0], xv.x);
        atomicAdd(&dwrow[c + 1], xv.y);
    }

    // loss partial: warp reduce double, one atomic per warp
    double lacc = (double)lsum;
    #pragma unroll
    for (int off = 16; off > 0; off >>= 1)
        lacc += __shfl_down_sync(0xffffffffu, lacc, off);
    if ((threadIdx.x & 31) == 0)
        atomicAdd(&g_loss, lacc);
}

// ---------------------------------------------------------------------------
// Kernel 2: finalize — EMA update, Laplace smoothing, perplexity, loss
// ---------------------------------------------------------------------------
__global__ void __launch_bounds__(NUM_EMBED)
vq_finalize_kernel(const float* __restrict__ embed_avg,
                   const float* __restrict__ cluster_size,
                   float* __restrict__ out)
{
    __shared__ float  s_smoothed[NUM_EMBED];
    __shared__ double s_red[NUM_EMBED];

    const int t = threadIdx.x;  // 512 threads

    const float cnt = g_counts[t];
    const float ncs = cluster_size[t] * DECAY + ONE_MINUS_DECAY * cnt;
    out[OFF_CS + t] = ncs;

    // n = sum(new_cluster_size)
    s_red[t] = (double)ncs;
    __syncthreads();
    #pragma unroll
    for (int off = NUM_EMBED / 2; off > 0; off >>= 1) {
        if (t < off) s_red[t] += s_red[t + off];
        __syncthreads();
    }
    const float nf = (float)s_red[0];
    __syncthreads();

    // smoothed = n * ((ncs + alpha) / (n + K*alpha))  in fp32 like reference
    s_smoothed[t] = nf * ((ncs + LAPLACE_ALPHA) / (nf + NUM_EMBED * LAPLACE_ALPHA));

    // perplexity from empirical usage
    const float p = cnt / (float)N_TOKENS;
    s_red[t] = (double)(p * logf(p + 1e-10f));
    __syncthreads();
    #pragma unroll
    for (int off = NUM_EMBED / 2; off > 0; off >>= 1) {
        if (t < off) s_red[t] += s_red[t + off];
        __syncthreads();
    }
    if (t == 0) {
        out[OFF_PERP] = expf(-(float)s_red[0]);
        const float mean_sq = (float)(g_loss / (double)Q_ELEMS);
        out[OFF_LOSS] = COMMIT_COST * mean_sq;
    }
    __syncthreads();

    // new_embed_avg / new_embed (coalesced grid-stride)
    for (int i = t; i < NUM_EMBED * EMBED_DIM; i += NUM_EMBED) {
        const float ea = embed_avg[i] * DECAY + ONE_MINUS_DECAY * g_dw[i];
        out[OFF_EA + i]       = ea;
        out[OFF_NEWEMBED + i] = ea / s_smoothed[i >> 6];
    }
}

// ---------------------------------------------------------------------------
// Launch
// ---------------------------------------------------------------------------
extern "C" void kernel_launch(void* const* d_in, const int* in_sizes, int n_in,
                              void* d_out, int out_size)
{
    const float* inputs       = (const float*)d_in[0];
    const float* embed        = (const float*)d_in[1];
    const float* embed_avg    = (const float*)d_in[2];
    const float* cluster_size = (const float*)d_in[3];
    float* out = (float*)d_out;

    cudaFuncSetAttribute(vq_main_kernel,
                         cudaFuncAttributeMaxDynamicSharedMemorySize, SMEM_BYTES);

    vq_zero_kernel<<<(NUM_EMBED * EMBED_DIM + 255) / 256, 256>>>();
    vq_main_kernel<<<MAIN_CTAS, MAIN_THREADS, SMEM_BYTES>>>(inputs, embed, out);
    vq_finalize_kernel<<<1, NUM_EMBED>>>(embed_avg, cluster_size, out);
}

// round 8
// speedup vs baseline: 1.3583x; 1.3583x over previous
#include <cuda_runtime.h>
#include <math.h>
#include <stdint.h>

// ---------------------------------------------------------------------------
// Problem constants
// ---------------------------------------------------------------------------
#define NUM_EMBED   512
#define EMBED_DIM   64
#define BATCH       4
#define SPATIAL     32768           // 32*32*32
#define N_TOKENS    (BATCH*SPATIAL) // 131072
#define Q_ELEMS     (BATCH*EMBED_DIM*SPATIAL) // 8388608

// Output offsets (tuple flattened, float32)
#define OFF_LOSS      0
#define OFF_Q         1
#define OFF_PERP      (OFF_Q + Q_ELEMS)
#define OFF_IDX       (OFF_PERP + 1)
#define OFF_NEWEMBED  (OFF_IDX + N_TOKENS)
#define OFF_CS        (OFF_NEWEMBED + NUM_EMBED*EMBED_DIM)
#define OFF_EA        (OFF_CS + NUM_EMBED)

#define DECAY           0.99f
#define ONE_MINUS_DECAY 0.01f
#define COMMIT_COST     0.25f
#define LAPLACE_ALPHA   1e-5f

// Virtual-K GEMM layout: K = 192 = 24 k-tiles of 8.
//   k in [0,64):    A = xhi[k],     B = ehi[k]
//   k in [64,128):  A = xlo[k-64],  B = ehi[k-64]
//   k in [128,192): A = xhi[k-128], B = elo[k-128]
#define PN  208    // packed B row stride in floats (per code)
#define QS  52     // per-q stride within a row (48 used + 4 pad -> bank spread)
#define CC  64     // codes per streamed chunk
#define NCHUNK (NUM_EMBED / CC)          // 8
#define CHUNK_BYTES (CC * PN * 4)        // 53248

// ---------------------------------------------------------------------------
// Scratch (device globals — no allocations allowed)
// ---------------------------------------------------------------------------
__device__ float  g_counts[NUM_EMBED];
__device__ float  g_dw[NUM_EMBED * EMBED_DIM];
__device__ double g_loss;
__device__ float  g_halfn[NUM_EMBED];                       // 0.5*||e||^2 exact
__device__ __align__(16) float g_bpack[NUM_EMBED * PN];     // packed tf32 B

// ---------------------------------------------------------------------------
// Helpers (all baseline sm_80+ PTX — no 'a'-suffix features)
// ---------------------------------------------------------------------------
__device__ __forceinline__ uint32_t smem_u32(const void* p) {
    uint32_t a;
    asm("{ .reg .u64 t; cvta.to.shared.u64 t, %1; cvt.u32.u64 %0, t; }"
        : "=r"(a) : "l"(p));
    return a;
}
__device__ __forceinline__ float tf32f(float x) {
    uint32_t u;
    asm("cvt.rna.tf32.f32 %0, %1;" : "=r"(u) : "f"(x));
    return __uint_as_float(u);
}
__device__ __forceinline__ void mma8(float d[4],
                                     uint32_t a0, uint32_t a1, uint32_t a2, uint32_t a3,
                                     uint32_t b0, uint32_t b1) {
    asm volatile(
        "mma.sync.aligned.m16n8k8.row.col.f32.tf32.tf32.f32 "
        "{%0,%1,%2,%3}, {%4,%5,%6,%7}, {%8,%9}, {%0,%1,%2,%3};"
        : "+f"(d[0]), "+f"(d[1]), "+f"(d[2]), "+f"(d[3])
        : "r"(a0), "r"(a1), "r"(a2), "r"(a3), "r"(b0), "r"(b1));
}
#define CP_ASYNC16(dst_smem_u32, src_gptr) \
    asm volatile("cp.async.cg.shared.global [%0], [%1], 16;" \
                 :: "r"(dst_smem_u32), "l"(src_gptr) : "memory")
#define CP_COMMIT() asm volatile("cp.async.commit_group;" ::: "memory")
#define CP_WAIT1()  asm volatile("cp.async.wait_group 1;" ::: "memory")

// ---------------------------------------------------------------------------
// Prep kernels
// ---------------------------------------------------------------------------
__global__ void vq_zero_kernel() {
    int i = blockIdx.x * blockDim.x + threadIdx.x;
    if (i < NUM_EMBED * EMBED_DIM) g_dw[i] = 0.0f;
    if (i < NUM_EMBED)             g_counts[i] = 0.0f;
    if (i == 0)                    g_loss = 0.0;
}

// Pack B in exact fragment-consumption order:
// row n (code), offset = q*QS + u*4 + kt1*2 + p, where ktile = 2u+kt1,
// virtual k = ktile*8 + q + p*4.
__global__ void vq_pack_b_kernel(const float* __restrict__ embed) {
    int idx = blockIdx.x * blockDim.x + threadIdx.x;   // over 512*192
    if (idx >= NUM_EMBED * 192) return;
    int n = idx / 192, r = idx % 192;
    int q = r / 48, t = r % 48;
    int u = t >> 2, kt1 = (t >> 1) & 1, p = t & 1;
    int ktile = 2 * u + kt1;
    int k = ktile * 8 + q + p * 4;                     // virtual k 0..191
    int c = k & 63;
    float e  = embed[n * EMBED_DIM + c];
    float hi = tf32f(e);
    float v  = (k < 128) ? hi : tf32f(e - hi);
    g_bpack[n * PN + q * QS + t] = v;
}

__global__ void __launch_bounds__(NUM_EMBED)
vq_halfn_kernel(const float* __restrict__ embed) {
    int k = threadIdx.x;
    const float* row = embed + k * EMBED_DIM;
    float s = 0.0f;
    #pragma unroll
    for (int c = 0; c < EMBED_DIM; c++) s = fmaf(row[c], row[c], s);
    g_halfn[k] = 0.5f * s;
}

// ---------------------------------------------------------------------------
// Main kernel: tf32 3-split mma.sync distance GEMM + argmin + exact epilogue
// Grid: 512 CTAs x 256 threads; 256 tokens per CTA (8 warps x 2 Mtiles x 16).
// ---------------------------------------------------------------------------
#define MAIN_THREADS 256
#define TPC          256
#define MAIN_CTAS    (N_TOKENS / TPC)   // 512

// smem layout
#define SM_HALFN 0        // 512 f32 = 2048 B
#define SM_BESTK 2048     // 256 i32 = 1024 B
#define SM_BUF   4096     // 2 x CHUNK_BYTES
#define SMEM_TOTAL (SM_BUF + 2 * CHUNK_BYTES)   // 110592

extern __shared__ char smem_raw[];

__global__ void __launch_bounds__(MAIN_THREADS, 1)
vq_main_kernel(const float* __restrict__ inputs,
               const float* __restrict__ embed,
               float* __restrict__ out)
{
    const uint32_t sb = smem_u32(smem_raw);
    const int tid  = threadIdx.x;
    const int wid  = tid >> 5;
    const int lane = tid & 31;
    const int q    = lane & 3;    // threadID_in_group (k-index / D-col pair)
    const int g    = lane >> 2;   // groupID (token row / B-col)

    float* sm_halfn = (float*)(smem_raw + SM_HALFN);
    int*   sm_bestk = (int*)(smem_raw + SM_BESTK);

    // ---- start streaming B chunks 0 and 1 immediately ----
    {
        const char* src = (const char*)g_bpack;
        #pragma unroll
        for (int i = 0; i < CHUNK_BYTES / 16 / MAIN_THREADS; i++) {
            int off = tid * 16 + i * (MAIN_THREADS * 16);
            CP_ASYNC16(sb + SM_BUF + off, src + off);
        }
        CP_COMMIT();
        #pragma unroll
        for (int i = 0; i < CHUNK_BYTES / 16 / MAIN_THREADS; i++) {
            int off = tid * 16 + i * (MAIN_THREADS * 16);
            CP_ASYNC16(sb + SM_BUF + CHUNK_BYTES + off, src + CHUNK_BYTES + off);
        }
        CP_COMMIT();
    }

    // halfn -> smem
    for (int k = tid; k < NUM_EMBED; k += MAIN_THREADS)
        sm_halfn[k] = g_halfn[k];

    // ---- A fragments: per thread 2 Mtiles x 2 rows x 16 cols, hi+lo ----
    const int n0 = blockIdx.x * TPC;
    const int bb = n0 >> 15;
    const int s0 = n0 & (SPATIAL - 1);
    const float* xbase = inputs + (size_t)bb * (EMBED_DIM * SPATIAL) + s0;

    uint32_t ahi[2][32], alo[2][32];
    #pragma unroll
    for (int m = 0; m < 2; m++) {
        #pragma unroll
        for (int h = 0; h < 2; h++) {
            const int tok = wid * 32 + m * 16 + h * 8 + g;
            #pragma unroll
            for (int kt = 0; kt < 8; kt++) {
                #pragma unroll
                for (int pp = 0; pp < 2; pp++) {
                    const int c = kt * 8 + q + pp * 4;
                    const float x  = xbase[(size_t)c * SPATIAL + tok];
                    const float hi = tf32f(x);
                    const float lo = tf32f(x - hi);
                    ahi[m][h * 16 + kt * 2 + pp] = __float_as_uint(hi);
                    alo[m][h * 16 + kt * 2 + pp] = __float_as_uint(lo);
                }
            }
        }
    }

    // per-thread argmin state: rows = m*16 + h*8 + g
    float best[2][2] = {{3.4e38f, 3.4e38f}, {3.4e38f, 3.4e38f}};
    int   bidx[2][2] = {{0, 0}, {0, 0}};

    // ---- chunk loop ----
    #pragma unroll 1
    for (int ch = 0; ch < NCHUNK; ch++) {
        CP_WAIT1();
        __syncthreads();
        const float* B = (const float*)(smem_raw + SM_BUF + (ch & 1) * CHUNK_BYTES);

        #pragma unroll 1
        for (int nt = 0; nt < 8; nt++) {
            float d0[4] = {0.f, 0.f, 0.f, 0.f};
            float d1[4] = {0.f, 0.f, 0.f, 0.f};
            const float* brow = B + (size_t)(nt * 8 + g) * PN + q * QS;

            #pragma unroll
            for (int u = 0; u < 12; u++) {
                const float4 bv = *(const float4*)(brow + u * 4);
                #pragma unroll
                for (int kk = 0; kk < 2; kk++) {
                    const int kt = 2 * u + kk;              // 0..23 (compile-time)
                    const uint32_t b0 = __float_as_uint(kk ? bv.z : bv.x);
                    const uint32_t b1 = __float_as_uint(kk ? bv.w : bv.y);
                    const int i0 = (kt & 7) * 2;
                    const bool useLo = (kt >= 8) && (kt < 16);
                    const uint32_t a00 = useLo ? alo[0][i0]      : ahi[0][i0];
                    const uint32_t a01 = useLo ? alo[0][16 + i0] : ahi[0][16 + i0];
                    const uint32_t a02 = useLo ? alo[0][i0 + 1]  : ahi[0][i0 + 1];
                    const uint32_t a03 = useLo ? alo[0][17 + i0] : ahi[0][17 + i0];
                    const uint32_t a10 = useLo ? alo[1][i0]      : ahi[1][i0];
                    const uint32_t a11 = useLo ? alo[1][16 + i0] : ahi[1][16 + i0];
                    const uint32_t a12 = useLo ? alo[1][i0 + 1]  : ahi[1][i0 + 1];
                    const uint32_t a13 = useLo ? alo[1][17 + i0] : ahi[1][17 + i0];
                    mma8(d0, a00, a01, a02, a03, b0, b1);
                    mma8(d1, a10, a11, a12, a13, b0, b1);
                }
            }

            // fold: D row = token row, col = code.  d0/d1 cols = 2q, 2q+1
            const int kb = ch * CC + nt * 8;
            const float2 hn = *(const float2*)(sm_halfn + kb + 2 * q);
            const int c0 = kb + 2 * q, c1 = c0 + 1;
            float dd;
            dd = hn.x - d0[0]; if (dd < best[0][0]) { best[0][0] = dd; bidx[0][0] = c0; }
            dd = hn.y - d0[1]; if (dd < best[0][0]) { best[0][0] = dd; bidx[0][0] = c1; }
            dd = hn.x - d0[2]; if (dd < best[0][1]) { best[0][1] = dd; bidx[0][1] = c0; }
            dd = hn.y - d0[3]; if (dd < best[0][1]) { best[0][1] = dd; bidx[0][1] = c1; }
            dd = hn.x - d1[0]; if (dd < best[1][0]) { best[1][0] = dd; bidx[1][0] = c0; }
            dd = hn.y - d1[1]; if (dd < best[1][0]) { best[1][0] = dd; bidx[1][0] = c1; }
            dd = hn.x - d1[2]; if (dd < best[1][1]) { best[1][1] = dd; bidx[1][1] = c0; }
            dd = hn.y - d1[3]; if (dd < best[1][1]) { best[1][1] = dd; bidx[1][1] = c1; }
        }

        __syncthreads();   // all warps done with buf[ch&1] before refill
        {
            const int nxt = ch + 2;
            if (nxt < NCHUNK) {
                const char* src = (const char*)g_bpack + (size_t)nxt * CHUNK_BYTES;
                #pragma unroll
                for (int i = 0; i < CHUNK_BYTES / 16 / MAIN_THREADS; i++) {
                    int off = tid * 16 + i * (MAIN_THREADS * 16);
                    CP_ASYNC16(sb + SM_BUF + (ch & 1) * CHUNK_BYTES + off, src + off);
                }
            }
            CP_COMMIT();   // commit every iteration (possibly empty) to keep counts
        }
    }

    // ---- quad reduction (lanes q=0..3 hold interleaved code subsets) ----
    #pragma unroll
    for (int m = 0; m < 2; m++) {
        #pragma unroll
        for (int h = 0; h < 2; h++) {
            float b = best[m][h];
            int   bi = bidx[m][h];
            #pragma unroll
            for (int delta = 1; delta <= 2; delta <<= 1) {
                const float ob = __shfl_down_sync(0xffffffffu, b, delta, 4);
                const int   oi = __shfl_down_sync(0xffffffffu, bi, delta, 4);
                if (ob < b || (ob == b && oi < bi)) { b = ob; bi = oi; }
            }
            if (q == 0)
                sm_bestk[wid * 32 + m * 16 + h * 8 + g] = bi;
        }
    }
    __syncthreads();

    // ---- exact fp32 epilogue: one token per thread (bit-identical to R3) ----
    {
        const int n = n0 + tid;
        const int k = sm_bestk[tid];
        out[OFF_IDX + n] = (float)k;
        atomicAdd(&g_counts[k], 1.0f);

        const float* er  = embed + (size_t)k * EMBED_DIM;
        const float* xin = xbase + tid;
        float* qout = out + OFF_Q + (size_t)bb * (EMBED_DIM * SPATIAL) + s0 + tid;
        float* dwr  = g_dw + (size_t)k * EMBED_DIM;

        float lsum = 0.0f;
        #pragma unroll 8
        for (int c = 0; c < EMBED_DIM; c++) {
            const float e = er[c];
            const float x = xin[(size_t)c * SPATIAL];
            const float d = e - x;                 // quantized_cf - inputs
            lsum = fmaf(d, d, lsum);
            qout[(size_t)c * SPATIAL] = x + d;     // straight-through rounding
            atomicAdd(&dwr[c], x);
        }
        double la = (double)lsum;
        #pragma unroll
        for (int off = 16; off > 0; off >>= 1)
            la += __shfl_down_sync(0xffffffffu, la, off);
        if (lane == 0) atomicAdd(&g_loss, la);
    }
}

// ---------------------------------------------------------------------------
// Finalize: EMA update, Laplace smoothing, perplexity, loss
// ---------------------------------------------------------------------------
__global__ void __launch_bounds__(NUM_EMBED)
vq_finalize_kernel(const float* __restrict__ embed_avg,
                   const float* __restrict__ cluster_size,
                   float* __restrict__ out)
{
    __shared__ float  s_smoothed[NUM_EMBED];
    __shared__ double s_red[NUM_EMBED];

    const int t = threadIdx.x;

    const float cnt = g_counts[t];
    const float ncs = cluster_size[t] * DECAY + ONE_MINUS_DECAY * cnt;
    out[OFF_CS + t] = ncs;

    s_red[t] = (double)ncs;
    __syncthreads();
    #pragma unroll
    for (int off = NUM_EMBED / 2; off > 0; off >>= 1) {
        if (t < off) s_red[t] += s_red[t + off];
        __syncthreads();
    }
    const float nf = (float)s_red[0];
    __syncthreads();

    s_smoothed[t] = nf * ((ncs + LAPLACE_ALPHA) / (nf + NUM_EMBED * LAPLACE_ALPHA));

    const float p = cnt / (float)N_TOKENS;
    s_red[t] = (double)(p * logf(p + 1e-10f));
    __syncthreads();
    #pragma unroll
    for (int off = NUM_EMBED / 2; off > 0; off >>= 1) {
        if (t < off) s_red[t] += s_red[t + off];
        __syncthreads();
    }
    if (t == 0) {
        out[OFF_PERP] = expf(-(float)s_red[0]);
        out[OFF_LOSS] = COMMIT_COST * (float)(g_loss / (double)Q_ELEMS);
    }
    __syncthreads();

    for (int i = t; i < NUM_EMBED * EMBED_DIM; i += NUM_EMBED) {
        const float ea = embed_avg[i] * DECAY + ONE_MINUS_DECAY * g_dw[i];
        out[OFF_EA + i]       = ea;
        out[OFF_NEWEMBED + i] = ea / s_smoothed[i >> 6];
    }
}

// ---------------------------------------------------------------------------
// Launch
// ---------------------------------------------------------------------------
extern "C" void kernel_launch(void* const* d_in, const int* in_sizes, int n_in,
                              void* d_out, int out_size)
{
    const float* inputs       = (const float*)d_in[0];
    const float* embed        = (const float*)d_in[1];
    const float* embed_avg    = (const float*)d_in[2];
    const float* cluster_size = (const float*)d_in[3];
    float* out = (float*)d_out;

    cudaFuncSetAttribute(vq_main_kernel,
                         cudaFuncAttributeMaxDynamicSharedMemorySize, SMEM_TOTAL);

    vq_zero_kernel<<<(NUM_EMBED * EMBED_DIM + 255) / 256, 256>>>();
    vq_pack_b_kernel<<<(NUM_EMBED * 192 + 255) / 256, 256>>>(embed);
    vq_halfn_kernel<<<1, NUM_EMBED>>>(embed);
    vq_main_kernel<<<MAIN_CTAS, MAIN_THREADS, SMEM_TOTAL>>>(inputs, embed, out);
    vq_finalize_kernel<<<1, NUM_EMBED>>>(embed_avg, cluster_size, out);
}